// round 1
// baseline (speedup 1.0000x reference)
#include <cuda_runtime.h>
#include <cstdint>

#define L_SEQ  1024
#define DMODEL 1024
#define DINNER 2048
#define NH     32
#define HD     64
#define NST    64
#define CONVD  2176
#define DPROJ  4256

// ---------------- scratch (static device globals; no allocations) ----------------
__device__ __align__(128) float g_zx [2 * L_SEQ * DPROJ];   // in_proj outputs, both dirs
__device__ __align__(128) float g_x  [2 * L_SEQ * DINNER];  // conv+silu x
__device__ __align__(128) float g_dtx[2 * L_SEQ * DINNER];  // dt * x
__device__ __align__(128) float g_dA [2 * L_SEQ * NH];
__device__ __align__(128) float g_Bv [2 * L_SEQ * NST];
__device__ __align__(128) float g_Cv [2 * L_SEQ * NST];
__device__ __align__(128) float g_y  [2 * L_SEQ * DINNER];  // scan output
__device__ __align__(128) float g_ygn[2 * L_SEQ * DINNER];  // gated + rmsnormed
__device__ __align__(128) float g_t  [2 * L_SEQ * DMODEL];  // per-dir out proj
__device__ __align__(128) float g_G  [L_SEQ * 2 * DMODEL];  // silu(concat)

// ---------------- helpers ----------------
__device__ __forceinline__ float silu_f(float v) { return v / (1.f + expf(-v)); }
__device__ __forceinline__ float softplus_f(float v) { return v > 20.f ? v : log1pf(expf(v)); }

__device__ __forceinline__ uint32_t f2tf(float x) {
    uint32_t r;
    asm("cvt.rna.tf32.f32 %0, %1;" : "=r"(r) : "f"(x));
    return r;
}

__device__ __forceinline__ void mma_tf32(float* c, const uint32_t* a, const uint32_t* b) {
    asm volatile(
        "mma.sync.aligned.m16n8k8.row.col.f32.tf32.tf32.f32 "
        "{%0,%1,%2,%3},{%4,%5,%6,%7},{%8,%9},{%0,%1,%2,%3};"
        : "+f"(c[0]), "+f"(c[1]), "+f"(c[2]), "+f"(c[3])
        : "r"(a[0]), "r"(a[1]), "r"(a[2]), "r"(a[3]), "r"(b[0]), "r"(b[1]));
}

// ---------------- tf32 GEMM: C[M,N] = A[M,K] @ W[N,K]^T ----------------
// BM=128, BN=64, BK=32, 256 threads (8 warps as 4x2), warp tile 32x32.
// Shared layout [row][k] stride 36 words -> bank = (4*row + k) mod 32 -> conflict-free frags.
#define LDS_STRIDE 36

__global__ __launch_bounds__(256) void gemm_tf32(
    const float* __restrict__ A, int lda, int flipA,
    const float* __restrict__ W, int ldw,
    float* __restrict__ C, int ldc,
    int M, int N, int K)
{
    __shared__ uint32_t As[128 * LDS_STRIDE];
    __shared__ uint32_t Bs[64 * LDS_STRIDE];

    const int tid  = threadIdx.x;
    const int warp = tid >> 5, lane = tid & 31;
    const int g = lane >> 2, tg = lane & 3;
    const int wm = warp >> 1, wn = warp & 1;     // 4 x 2 warp grid
    const int mblk = blockIdx.y * 128;
    const int nblk = blockIdx.x * 64;
    const int m0 = wm * 32, n0 = wn * 32;

    float acc[2][4][4];
#pragma unroll
    for (int i = 0; i < 2; i++)
#pragma unroll
        for (int j = 0; j < 4; j++)
#pragma unroll
            for (int r = 0; r < 4; r++) acc[i][j][r] = 0.f;

    for (int kt = 0; kt < K; kt += 32) {
        // load A tile 128x32
#pragma unroll
        for (int i = 0; i < 4; i++) {
            int idx = tid + i * 256;
            int m = idx >> 3, kg = (idx & 7) << 2;
            int gr = mblk + m;
            int row = flipA ? (M - 1 - gr) : gr;
            float4 v = *reinterpret_cast<const float4*>(A + (size_t)row * lda + kt + kg);
            uint32_t* d = &As[m * LDS_STRIDE + kg];
            d[0] = f2tf(v.x); d[1] = f2tf(v.y); d[2] = f2tf(v.z); d[3] = f2tf(v.w);
        }
        // load W tile 64x32 (guard N)
#pragma unroll
        for (int i = 0; i < 2; i++) {
            int idx = tid + i * 256;
            int n = idx >> 3, kg = (idx & 7) << 2;
            int gn = nblk + n;
            float4 v = make_float4(0.f, 0.f, 0.f, 0.f);
            if (gn < N) v = *reinterpret_cast<const float4*>(W + (size_t)gn * ldw + kt + kg);
            uint32_t* d = &Bs[n * LDS_STRIDE + kg];
            d[0] = f2tf(v.x); d[1] = f2tf(v.y); d[2] = f2tf(v.z); d[3] = f2tf(v.w);
        }
        __syncthreads();

#pragma unroll
        for (int ks = 0; ks < 4; ks++) {
            const int k0 = ks * 8;
            uint32_t a[2][4], b[4][2];
#pragma unroll
            for (int mt = 0; mt < 2; mt++) {
                int row = m0 + mt * 16 + g;
                a[mt][0] = As[row * LDS_STRIDE + k0 + tg];
                a[mt][1] = As[(row + 8) * LDS_STRIDE + k0 + tg];
                a[mt][2] = As[row * LDS_STRIDE + k0 + tg + 4];
                a[mt][3] = As[(row + 8) * LDS_STRIDE + k0 + tg + 4];
            }
#pragma unroll
            for (int nt = 0; nt < 4; nt++) {
                int col = n0 + nt * 8 + g;
                b[nt][0] = Bs[col * LDS_STRIDE + k0 + tg];
                b[nt][1] = Bs[col * LDS_STRIDE + k0 + tg + 4];
            }
#pragma unroll
            for (int mt = 0; mt < 2; mt++)
#pragma unroll
                for (int nt = 0; nt < 4; nt++)
                    mma_tf32(acc[mt][nt], a[mt], b[nt]);
        }
        __syncthreads();
    }

    // epilogue
#pragma unroll
    for (int mt = 0; mt < 2; mt++) {
#pragma unroll
        for (int nt = 0; nt < 4; nt++) {
            int row = mblk + m0 + mt * 16 + g;
            int col = nblk + n0 + nt * 8 + 2 * tg;
            if (col < N) {
                C[(size_t)row * ldc + col]           = acc[mt][nt][0];
                C[(size_t)(row + 8) * ldc + col]     = acc[mt][nt][2];
            }
            if (col + 1 < N) {
                C[(size_t)row * ldc + col + 1]       = acc[mt][nt][1];
                C[(size_t)(row + 8) * ldc + col + 1] = acc[mt][nt][3];
            }
        }
    }
}

// ---------------- prep: causal dwconv + silu, dt softplus, dA, dtx ----------------
__global__ __launch_bounds__(256) void prep_kernel(
    const float* __restrict__ cw_f, const float* __restrict__ cb_f,
    const float* __restrict__ cw_b, const float* __restrict__ cb_b,
    const float* __restrict__ dtb_f, const float* __restrict__ dtb_b,
    const float* __restrict__ Alog_f, const float* __restrict__ Alog_b)
{
    const int l = blockIdx.x, dir = blockIdx.y, tid = threadIdx.x;
    const float* cw   = dir ? cw_b   : cw_f;
    const float* cb   = dir ? cb_b   : cb_f;
    const float* dtb  = dir ? dtb_b  : dtb_f;
    const float* Alog = dir ? Alog_b : Alog_f;

    const size_t base = (size_t)dir * L_SEQ + l;
    const float* zrow = g_zx + base * DPROJ;

    __shared__ float sdt[NH];
    if (tid < NH) {
        float dt = softplus_f(zrow[4224 + tid] + dtb[tid]);
        sdt[tid] = dt;
        g_dA[base * NH + tid] = expf(-expf(Alog[tid]) * dt);
    }
    __syncthreads();

    for (int c = tid; c < CONVD; c += 256) {
        float s = cb[c];
#pragma unroll
        for (int t = 0; t < 4; t++) {
            int lp = l - 3 + t;
            if (lp >= 0)
                s = fmaf(cw[c * 4 + t],
                         g_zx[((size_t)dir * L_SEQ + lp) * DPROJ + 2048 + c], s);
        }
        float v = silu_f(s);
        if (c < DINNER) {
            g_x[base * DINNER + c]   = v;
            g_dtx[base * DINNER + c] = sdt[c >> 6] * v;
        } else if (c < 2112) {
            g_Bv[base * NST + (c - 2048)] = v;
        } else {
            g_Cv[base * NST + (c - 2112)] = v;
        }
    }
}

// ---------------- sequential SSM scan ----------------
// grid (2 p-slices, 32 heads, 2 dirs) = 128 blocks, 128 threads.
// thread t: p_local = t>>2 (0..31), q = t&3 owns n in [q*16, q*16+16).
__global__ __launch_bounds__(128) void scan_kernel()
{
    const int ps = blockIdx.x, hh = blockIdx.y, dir = blockIdx.z;
    const int tid = threadIdx.x;
    const int pl = tid >> 2, q = tid & 3;

    __shared__ float sB[8][64], sC[8][64], sdt[8][32], sdA[8];

    float h[16];
#pragma unroll
    for (int j = 0; j < 16; j++) h[j] = 0.f;

    const size_t dbase = (size_t)dir * L_SEQ;
    const int pcol = hh * HD + ps * 32;

    for (int c0 = 0; c0 < L_SEQ; c0 += 8) {
        for (int idx = tid; idx < 8 * 64; idx += 128) {
            int s = idx >> 6, n = idx & 63;
            sB[s][n] = g_Bv[(dbase + c0 + s) * NST + n];
            sC[s][n] = g_Cv[(dbase + c0 + s) * NST + n];
        }
        for (int idx = tid; idx < 8 * 32; idx += 128) {
            int s = idx >> 5, pp = idx & 31;
            sdt[s][pp] = g_dtx[(dbase + c0 + s) * DINNER + pcol + pp];
        }
        if (tid < 8) sdA[tid] = g_dA[(dbase + c0 + tid) * NH + hh];
        __syncthreads();

#pragma unroll 1
        for (int s = 0; s < 8; s++) {
            const float dA = sdA[s];
            const float dtx = sdt[s][pl];
            float accv = 0.f;
#pragma unroll
            for (int j = 0; j < 16; j++) {
                int n = q * 16 + j;
                h[j] = fmaf(h[j], dA, dtx * sB[s][n]);
                accv = fmaf(h[j], sC[s][n], accv);
            }
            accv += __shfl_xor_sync(0xffffffffu, accv, 1);
            accv += __shfl_xor_sync(0xffffffffu, accv, 2);
            if (q == 0)
                g_y[(dbase + c0 + s) * DINNER + pcol + pl] = accv;
        }
        __syncthreads();
    }
}

// ---------------- gate: y + D*x, *silu(z), rmsnorm, *norm_w ----------------
__global__ __launch_bounds__(256) void gate_kernel(
    const float* __restrict__ D_f, const float* __restrict__ D_b,
    const float* __restrict__ nw_f, const float* __restrict__ nw_b)
{
    const int l = blockIdx.x, dir = blockIdx.y, tid = threadIdx.x;
    const float* Dp = dir ? D_b : D_f;
    const float* nw = dir ? nw_b : nw_f;
    const size_t base = (size_t)dir * L_SEQ + l;

    float ss = 0.f;
    for (int c = tid; c < DINNER; c += 256) {
        float y = g_y[base * DINNER + c] + Dp[c >> 6] * g_x[base * DINNER + c];
        float z = g_zx[base * DPROJ + c];
        float yg = y * silu_f(z);
        g_ygn[base * DINNER + c] = yg;
        ss = fmaf(yg, yg, ss);
    }
    __shared__ float red[8];
#pragma unroll
    for (int o = 16; o; o >>= 1) ss += __shfl_xor_sync(0xffffffffu, ss, o);
    if ((tid & 31) == 0) red[tid >> 5] = ss;
    __syncthreads();
    if (tid < 8) {
        float v = red[tid];
#pragma unroll
        for (int o = 4; o; o >>= 1) v += __shfl_xor_sync(0xffu, v, o);
        if (tid == 0) red[0] = v;
    }
    __syncthreads();
    const float scale = rsqrtf(red[0] * (1.f / DINNER) + 1e-5f);
    for (int c = tid; c < DINNER; c += 256)
        g_ygn[base * DINNER + c] *= scale * nw[c];
}

// ---------------- combine: silu(concat(out_f, flip(out_b))) ----------------
__global__ __launch_bounds__(256) void combine_kernel()
{
    const int l = blockIdx.x, tid = threadIdx.x;
    for (int j = tid; j < 2 * DMODEL; j += 256) {
        float v = (j < DMODEL)
            ? g_t[(size_t)l * DMODEL + j]
            : g_t[(size_t)(L_SEQ + (L_SEQ - 1 - l)) * DMODEL + (j - DMODEL)];
        g_G[(size_t)l * 2 * DMODEL + j] = silu_f(v);
    }
}

// ---------------- launch ----------------
extern "C" void kernel_launch(void* const* d_in, const int* in_sizes, int n_in,
                              void* d_out, int out_size)
{
    const float* u         = (const float*)d_in[0];
    const float* W_in_f    = (const float*)d_in[1];
    const float* W_in_b    = (const float*)d_in[2];
    const float* conv_w_f  = (const float*)d_in[3];
    const float* conv_b_f  = (const float*)d_in[4];
    const float* conv_w_b  = (const float*)d_in[5];
    const float* conv_b_b  = (const float*)d_in[6];
    const float* dt_bias_f = (const float*)d_in[7];
    const float* dt_bias_b = (const float*)d_in[8];
    const float* A_log_f   = (const float*)d_in[9];
    const float* A_log_b   = (const float*)d_in[10];
    const float* D_f       = (const float*)d_in[11];
    const float* D_b       = (const float*)d_in[12];
    const float* norm_w_f  = (const float*)d_in[13];
    const float* norm_w_b  = (const float*)d_in[14];
    const float* W_out_f   = (const float*)d_in[15];
    const float* W_out_b   = (const float*)d_in[16];
    const float* W_out     = (const float*)d_in[17];

    float *zx, *ygn, *tbuf, *Gm;
    cudaGetSymbolAddress((void**)&zx,   g_zx);
    cudaGetSymbolAddress((void**)&ygn,  g_ygn);
    cudaGetSymbolAddress((void**)&tbuf, g_t);
    cudaGetSymbolAddress((void**)&Gm,   g_G);

    // 1) in_proj both directions (dir1 reads time-flipped u)
    gemm_tf32<<<dim3((DPROJ + 63) / 64, L_SEQ / 128), 256>>>(
        u, DMODEL, 0, W_in_f, DMODEL, zx, DPROJ, L_SEQ, DPROJ, DMODEL);
    gemm_tf32<<<dim3((DPROJ + 63) / 64, L_SEQ / 128), 256>>>(
        u, DMODEL, 1, W_in_b, DMODEL, zx + (size_t)L_SEQ * DPROJ, DPROJ, L_SEQ, DPROJ, DMODEL);

    // 2) conv + silu + dt/dA/dtx
    prep_kernel<<<dim3(L_SEQ, 2), 256>>>(conv_w_f, conv_b_f, conv_w_b, conv_b_b,
                                         dt_bias_f, dt_bias_b, A_log_f, A_log_b);

    // 3) sequential scan
    scan_kernel<<<dim3(2, NH, 2), 128>>>();

    // 4) gate + rmsnorm
    gate_kernel<<<dim3(L_SEQ, 2), 256>>>(D_f, D_b, norm_w_f, norm_w_b);

    // 5) per-direction out projections
    gemm_tf32<<<dim3(DMODEL / 64, L_SEQ / 128), 256>>>(
        ygn, DINNER, 0, W_out_f, DINNER, tbuf, DMODEL, L_SEQ, DMODEL, DINNER);
    gemm_tf32<<<dim3(DMODEL / 64, L_SEQ / 128), 256>>>(
        ygn + (size_t)L_SEQ * DINNER, DINNER, 0, W_out_b, DINNER,
        tbuf + (size_t)L_SEQ * DMODEL, DMODEL, L_SEQ, DMODEL, DINNER);

    // 6) silu(concat) then final projection
    combine_kernel<<<L_SEQ, 256>>>();
    gemm_tf32<<<dim3(DMODEL / 64, L_SEQ / 128), 256>>>(
        Gm, 2 * DMODEL, 0, W_out, 2 * DMODEL, (float*)d_out, DMODEL,
        L_SEQ, DMODEL, 2 * DMODEL);
}

// round 2
// speedup vs baseline: 1.2825x; 1.2825x over previous
#include <cuda_runtime.h>
#include <cstdint>

#define L_SEQ  1024
#define DMODEL 1024
#define DINNER 2048
#define NH     32
#define HD     64
#define NST    64
#define CONVD  2176
#define DPROJ  4256

// ---------------- scratch (static device globals; no allocations) ----------------
__device__ __align__(128) float g_zx [2 * L_SEQ * DPROJ];   // in_proj outputs, both dirs
__device__ __align__(128) float g_x  [2 * L_SEQ * DINNER];  // conv+silu x
__device__ __align__(128) float g_dtx[2 * L_SEQ * DINNER];  // dt * x
__device__ __align__(128) float g_dA [2 * L_SEQ * NH];
__device__ __align__(128) float g_Bv [2 * L_SEQ * NST];
__device__ __align__(128) float g_Cv [2 * L_SEQ * NST];
__device__ __align__(128) float g_y  [2 * L_SEQ * DINNER];  // scan output
__device__ __align__(128) float g_ygn[2 * L_SEQ * DINNER];  // gated + rmsnormed
__device__ __align__(128) float g_t  [2 * L_SEQ * DMODEL];  // per-dir out proj
__device__ __align__(128) float g_G  [L_SEQ * 2 * DMODEL];  // silu(concat)

// ---------------- helpers ----------------
__device__ __forceinline__ float silu_f(float v) { return v / (1.f + expf(-v)); }
__device__ __forceinline__ float softplus_f(float v) { return v > 20.f ? v : log1pf(expf(v)); }

__device__ __forceinline__ uint32_t f2tf(float x) {
    uint32_t r;
    asm("cvt.rna.tf32.f32 %0, %1;" : "=r"(r) : "f"(x));
    return r;
}

__device__ __forceinline__ void mma_tf32(float* c, const uint32_t* a, const uint32_t* b) {
    asm volatile(
        "mma.sync.aligned.m16n8k8.row.col.f32.tf32.tf32.f32 "
        "{%0,%1,%2,%3},{%4,%5,%6,%7},{%8,%9},{%0,%1,%2,%3};"
        : "+f"(c[0]), "+f"(c[1]), "+f"(c[2]), "+f"(c[3])
        : "r"(a[0]), "r"(a[1]), "r"(a[2]), "r"(a[3]), "r"(b[0]), "r"(b[1]));
}

// packed fp32x2 ops (sm_103a FFMA2 path — PTX-only)
typedef unsigned long long u64t;
__device__ __forceinline__ u64t pk2(float v) {
    u64t r; asm("mov.b64 %0, {%1, %1};" : "=l"(r) : "f"(v)); return r;
}
__device__ __forceinline__ u64t fma2(u64t a, u64t b, u64t c) {
    u64t d; asm("fma.rn.f32x2 %0, %1, %2, %3;" : "=l"(d) : "l"(a), "l"(b), "l"(c)); return d;
}
__device__ __forceinline__ u64t mul2(u64t a, u64t b) {
    u64t d; asm("mul.rn.f32x2 %0, %1, %2;" : "=l"(d) : "l"(a), "l"(b)); return d;
}
__device__ __forceinline__ float hadd2(u64t a) {
    float lo, hi; asm("mov.b64 {%0, %1}, %2;" : "=f"(lo), "=f"(hi) : "l"(a)); return lo + hi;
}

// ---------------- tf32 GEMM: C[M,N] = A[M,K] @ W[N,K]^T ----------------
#define LDS_STRIDE 36

__global__ __launch_bounds__(256) void gemm_tf32(
    const float* __restrict__ A, int lda, int flipA,
    const float* __restrict__ W, int ldw,
    float* __restrict__ C, int ldc,
    int M, int N, int K)
{
    __shared__ uint32_t As[128 * LDS_STRIDE];
    __shared__ uint32_t Bs[64 * LDS_STRIDE];

    const int tid  = threadIdx.x;
    const int warp = tid >> 5, lane = tid & 31;
    const int g = lane >> 2, tg = lane & 3;
    const int wm = warp >> 1, wn = warp & 1;
    const int mblk = blockIdx.y * 128;
    const int nblk = blockIdx.x * 64;
    const int m0 = wm * 32, n0 = wn * 32;

    float acc[2][4][4];
#pragma unroll
    for (int i = 0; i < 2; i++)
#pragma unroll
        for (int j = 0; j < 4; j++)
#pragma unroll
            for (int r = 0; r < 4; r++) acc[i][j][r] = 0.f;

    for (int kt = 0; kt < K; kt += 32) {
#pragma unroll
        for (int i = 0; i < 4; i++) {
            int idx = tid + i * 256;
            int m = idx >> 3, kg = (idx & 7) << 2;
            int gr = mblk + m;
            int row = flipA ? (M - 1 - gr) : gr;
            float4 v = *reinterpret_cast<const float4*>(A + (size_t)row * lda + kt + kg);
            uint32_t* d = &As[m * LDS_STRIDE + kg];
            d[0] = f2tf(v.x); d[1] = f2tf(v.y); d[2] = f2tf(v.z); d[3] = f2tf(v.w);
        }
#pragma unroll
        for (int i = 0; i < 2; i++) {
            int idx = tid + i * 256;
            int n = idx >> 3, kg = (idx & 7) << 2;
            int gn = nblk + n;
            float4 v = make_float4(0.f, 0.f, 0.f, 0.f);
            if (gn < N) v = *reinterpret_cast<const float4*>(W + (size_t)gn * ldw + kt + kg);
            uint32_t* d = &Bs[n * LDS_STRIDE + kg];
            d[0] = f2tf(v.x); d[1] = f2tf(v.y); d[2] = f2tf(v.z); d[3] = f2tf(v.w);
        }
        __syncthreads();

#pragma unroll
        for (int ks = 0; ks < 4; ks++) {
            const int k0 = ks * 8;
            uint32_t a[2][4], b[4][2];
#pragma unroll
            for (int mt = 0; mt < 2; mt++) {
                int row = m0 + mt * 16 + g;
                a[mt][0] = As[row * LDS_STRIDE + k0 + tg];
                a[mt][1] = As[(row + 8) * LDS_STRIDE + k0 + tg];
                a[mt][2] = As[row * LDS_STRIDE + k0 + tg + 4];
                a[mt][3] = As[(row + 8) * LDS_STRIDE + k0 + tg + 4];
            }
#pragma unroll
            for (int nt = 0; nt < 4; nt++) {
                int col = n0 + nt * 8 + g;
                b[nt][0] = Bs[col * LDS_STRIDE + k0 + tg];
                b[nt][1] = Bs[col * LDS_STRIDE + k0 + tg + 4];
            }
#pragma unroll
            for (int mt = 0; mt < 2; mt++)
#pragma unroll
                for (int nt = 0; nt < 4; nt++)
                    mma_tf32(acc[mt][nt], a[mt], b[nt]);
        }
        __syncthreads();
    }

#pragma unroll
    for (int mt = 0; mt < 2; mt++) {
#pragma unroll
        for (int nt = 0; nt < 4; nt++) {
            int row = mblk + m0 + mt * 16 + g;
            int col = nblk + n0 + nt * 8 + 2 * tg;
            if (col < N) {
                C[(size_t)row * ldc + col]           = acc[mt][nt][0];
                C[(size_t)(row + 8) * ldc + col]     = acc[mt][nt][2];
            }
            if (col + 1 < N) {
                C[(size_t)row * ldc + col + 1]       = acc[mt][nt][1];
                C[(size_t)(row + 8) * ldc + col + 1] = acc[mt][nt][3];
            }
        }
    }
}

// ---------------- prep: causal dwconv + silu, dt softplus, dA, dtx ----------------
__global__ __launch_bounds__(256) void prep_kernel(
    const float* __restrict__ cw_f, const float* __restrict__ cb_f,
    const float* __restrict__ cw_b, const float* __restrict__ cb_b,
    const float* __restrict__ dtb_f, const float* __restrict__ dtb_b,
    const float* __restrict__ Alog_f, const float* __restrict__ Alog_b)
{
    const int l = blockIdx.x, dir = blockIdx.y, tid = threadIdx.x;
    const float* cw   = dir ? cw_b   : cw_f;
    const float* cb   = dir ? cb_b   : cb_f;
    const float* dtb  = dir ? dtb_b  : dtb_f;
    const float* Alog = dir ? Alog_b : Alog_f;

    const size_t base = (size_t)dir * L_SEQ + l;
    const float* zrow = g_zx + base * DPROJ;

    __shared__ float sdt[NH];
    if (tid < NH) {
        float dt = softplus_f(zrow[4224 + tid] + dtb[tid]);
        sdt[tid] = dt;
        g_dA[base * NH + tid] = expf(-expf(Alog[tid]) * dt);
    }
    __syncthreads();

    for (int c = tid; c < CONVD; c += 256) {
        float s = cb[c];
#pragma unroll
        for (int t = 0; t < 4; t++) {
            int lp = l - 3 + t;
            if (lp >= 0)
                s = fmaf(cw[c * 4 + t],
                         g_zx[((size_t)dir * L_SEQ + lp) * DPROJ + 2048 + c], s);
        }
        float v = silu_f(s);
        if (c < DINNER) {
            g_x[base * DINNER + c]   = v;
            g_dtx[base * DINNER + c] = sdt[c >> 6] * v;
        } else if (c < 2112) {
            g_Bv[base * NST + (c - 2048)] = v;
        } else {
            g_Cv[base * NST + (c - 2112)] = v;
        }
    }
}

// ---------------- sequential SSM scan (f32x2 packed, 16-step chunks) ----------------
// grid (2 p-slices, 32 heads, 2 dirs) = 128 blocks, 128 threads.
// thread t: pl = t>>2 (p within slice, 0..31), q = t&3 owns n in [q*16, q*16+16) = 8 pairs.
#define SCH 16

__global__ __launch_bounds__(128) void scan_kernel()
{
    const int ps = blockIdx.x, hh = blockIdx.y, dir = blockIdx.z;
    const int tid = threadIdx.x;
    const int pl = tid >> 2, q = tid & 3;

    __shared__ float sB[SCH][64], sC[SCH][64], sdt[SCH][32], sdA[SCH];

    u64t h[8];
#pragma unroll
    for (int j = 0; j < 8; j++) h[j] = 0ull;

    const size_t dbase = (size_t)dir * L_SEQ;
    const int pcol = hh * HD + ps * 32;

    for (int c0 = 0; c0 < L_SEQ; c0 += SCH) {
        // stage chunk: B/C are contiguous across the SCH steps
        {
            const float4* gb = reinterpret_cast<const float4*>(g_Bv + (dbase + c0) * NST);
            const float4* gc = reinterpret_cast<const float4*>(g_Cv + (dbase + c0) * NST);
            reinterpret_cast<float4*>(sB)[tid]       = gb[tid];
            reinterpret_cast<float4*>(sB)[tid + 128] = gb[tid + 128];
            reinterpret_cast<float4*>(sC)[tid]       = gc[tid];
            reinterpret_cast<float4*>(sC)[tid + 128] = gc[tid + 128];
            int s = tid >> 3, cc = (tid & 7) << 2;
            *reinterpret_cast<float4*>(&sdt[s][cc]) =
                *reinterpret_cast<const float4*>(g_dtx + (dbase + c0 + s) * DINNER + pcol + cc);
            if (tid < SCH) sdA[tid] = g_dA[(dbase + c0 + tid) * NH + hh];
        }
        __syncthreads();

#pragma unroll
        for (int s = 0; s < SCH; s++) {
            const u64t dA2 = pk2(sdA[s]);
            const u64t dt2 = pk2(sdt[s][pl]);
            const ulonglong2* Bp = reinterpret_cast<const ulonglong2*>(&sB[s][q * 16]);
            const ulonglong2* Cp = reinterpret_cast<const ulonglong2*>(&sC[s][q * 16]);
            u64t acc = 0ull;
#pragma unroll
            for (int j = 0; j < 4; j++) {
                ulonglong2 b2 = Bp[j];
                ulonglong2 c2 = Cp[j];
                h[2 * j]     = fma2(h[2 * j],     dA2, mul2(dt2, b2.x));
                acc          = fma2(h[2 * j],     c2.x, acc);
                h[2 * j + 1] = fma2(h[2 * j + 1], dA2, mul2(dt2, b2.y));
                acc          = fma2(h[2 * j + 1], c2.y, acc);
            }
            float a = hadd2(acc);
            a += __shfl_xor_sync(0xffffffffu, a, 1);
            a += __shfl_xor_sync(0xffffffffu, a, 2);
            if (q == 0)
                g_y[(dbase + c0 + s) * DINNER + pcol + pl] = a;
        }
        __syncthreads();
    }
}

// ---------------- gate: y + D*x, *silu(z), rmsnorm, *norm_w ----------------
__global__ __launch_bounds__(256) void gate_kernel(
    const float* __restrict__ D_f, const float* __restrict__ D_b,
    const float* __restrict__ nw_f, const float* __restrict__ nw_b)
{
    const int l = blockIdx.x, dir = blockIdx.y, tid = threadIdx.x;
    const float* Dp = dir ? D_b : D_f;
    const float* nw = dir ? nw_b : nw_f;
    const size_t base = (size_t)dir * L_SEQ + l;

    float ss = 0.f;
    for (int c = tid; c < DINNER; c += 256) {
        float y = g_y[base * DINNER + c] + Dp[c >> 6] * g_x[base * DINNER + c];
        float z = g_zx[base * DPROJ + c];
        float yg = y * silu_f(z);
        g_ygn[base * DINNER + c] = yg;
        ss = fmaf(yg, yg, ss);
    }
    __shared__ float red[8];
#pragma unroll
    for (int o = 16; o; o >>= 1) ss += __shfl_xor_sync(0xffffffffu, ss, o);
    if ((tid & 31) == 0) red[tid >> 5] = ss;
    __syncthreads();
    if (tid < 8) {
        float v = red[tid];
#pragma unroll
        for (int o = 4; o; o >>= 1) v += __shfl_xor_sync(0xffu, v, o);
        if (tid == 0) red[0] = v;
    }
    __syncthreads();
    const float scale = rsqrtf(red[0] * (1.f / DINNER) + 1e-5f);
    for (int c = tid; c < DINNER; c += 256)
        g_ygn[base * DINNER + c] *= scale * nw[c];
}

// ---------------- combine: silu(concat(out_f, flip(out_b))) ----------------
__global__ __launch_bounds__(256) void combine_kernel()
{
    const int l = blockIdx.x, tid = threadIdx.x;
    for (int j = tid; j < 2 * DMODEL; j += 256) {
        float v = (j < DMODEL)
            ? g_t[(size_t)l * DMODEL + j]
            : g_t[(size_t)(L_SEQ + (L_SEQ - 1 - l)) * DMODEL + (j - DMODEL)];
        g_G[(size_t)l * 2 * DMODEL + j] = silu_f(v);
    }
}

// ---------------- launch ----------------
extern "C" void kernel_launch(void* const* d_in, const int* in_sizes, int n_in,
                              void* d_out, int out_size)
{
    const float* u         = (const float*)d_in[0];
    const float* W_in_f    = (const float*)d_in[1];
    const float* W_in_b    = (const float*)d_in[2];
    const float* conv_w_f  = (const float*)d_in[3];
    const float* conv_b_f  = (const float*)d_in[4];
    const float* conv_w_b  = (const float*)d_in[5];
    const float* conv_b_b  = (const float*)d_in[6];
    const float* dt_bias_f = (const float*)d_in[7];
    const float* dt_bias_b = (const float*)d_in[8];
    const float* A_log_f   = (const float*)d_in[9];
    const float* A_log_b   = (const float*)d_in[10];
    const float* D_f       = (const float*)d_in[11];
    const float* D_b       = (const float*)d_in[12];
    const float* norm_w_f  = (const float*)d_in[13];
    const float* norm_w_b  = (const float*)d_in[14];
    const float* W_out_f   = (const float*)d_in[15];
    const float* W_out_b   = (const float*)d_in[16];
    const float* W_out     = (const float*)d_in[17];

    float *zx, *ygn, *tbuf, *Gm;
    cudaGetSymbolAddress((void**)&zx,   g_zx);
    cudaGetSymbolAddress((void**)&ygn,  g_ygn);
    cudaGetSymbolAddress((void**)&tbuf, g_t);
    cudaGetSymbolAddress((void**)&Gm,   g_G);

    // 1) in_proj both directions (dir1 reads time-flipped u)
    gemm_tf32<<<dim3((DPROJ + 63) / 64, L_SEQ / 128), 256>>>(
        u, DMODEL, 0, W_in_f, DMODEL, zx, DPROJ, L_SEQ, DPROJ, DMODEL);
    gemm_tf32<<<dim3((DPROJ + 63) / 64, L_SEQ / 128), 256>>>(
        u, DMODEL, 1, W_in_b, DMODEL, zx + (size_t)L_SEQ * DPROJ, DPROJ, L_SEQ, DPROJ, DMODEL);

    // 2) conv + silu + dt/dA/dtx
    prep_kernel<<<dim3(L_SEQ, 2), 256>>>(conv_w_f, conv_b_f, conv_w_b, conv_b_b,
                                         dt_bias_f, dt_bias_b, A_log_f, A_log_b);

    // 3) sequential scan
    scan_kernel<<<dim3(2, NH, 2), 128>>>();

    // 4) gate + rmsnorm
    gate_kernel<<<dim3(L_SEQ, 2), 256>>>(D_f, D_b, norm_w_f, norm_w_b);

    // 5) per-direction out projections
    gemm_tf32<<<dim3(DMODEL / 64, L_SEQ / 128), 256>>>(
        ygn, DINNER, 0, W_out_f, DINNER, tbuf, DMODEL, L_SEQ, DMODEL, DINNER);
    gemm_tf32<<<dim3(DMODEL / 64, L_SEQ / 128), 256>>>(
        ygn + (size_t)L_SEQ * DINNER, DINNER, 0, W_out_b, DINNER,
        tbuf + (size_t)L_SEQ * DMODEL, DMODEL, L_SEQ, DMODEL, DINNER);

    // 6) silu(concat) then final projection
    combine_kernel<<<L_SEQ, 256>>>();
    gemm_tf32<<<dim3(DMODEL / 64, L_SEQ / 128), 256>>>(
        Gm, 2 * DMODEL, 0, W_out, 2 * DMODEL, (float*)d_out, DMODEL,
        L_SEQ, DMODEL, 2 * DMODEL);
}

// round 3
// speedup vs baseline: 1.6193x; 1.2627x over previous
#include <cuda_runtime.h>
#include <cstdint>

#define L_SEQ  1024
#define DMODEL 1024
#define DINNER 2048
#define NH     32
#define HD     64
#define NST    64
#define CONVD  2176
#define DPROJ  4256

// ---------------- scratch (static device globals; no allocations) ----------------
__device__ __align__(128) float g_zx [2 * L_SEQ * DPROJ];
__device__ __align__(128) float g_x  [2 * L_SEQ * DINNER];
__device__ __align__(128) float g_dtx[2 * L_SEQ * DINNER];
__device__ __align__(128) float g_dA [2 * L_SEQ * NH];
__device__ __align__(128) float g_Bv [2 * L_SEQ * NST];
__device__ __align__(128) float g_Cv [2 * L_SEQ * NST];
__device__ __align__(128) float g_y  [2 * L_SEQ * DINNER];
__device__ __align__(128) float g_ygn[2 * L_SEQ * DINNER];
__device__ __align__(128) float g_t  [2 * L_SEQ * DMODEL];
__device__ __align__(128) float g_G  [L_SEQ * 2 * DMODEL];

// ---------------- helpers ----------------
__device__ __forceinline__ float silu_f(float v) { return v / (1.f + expf(-v)); }
__device__ __forceinline__ float softplus_f(float v) { return v > 20.f ? v : log1pf(expf(v)); }

__device__ __forceinline__ uint32_t f2tf(float x) {
    uint32_t r;
    asm("cvt.rna.tf32.f32 %0, %1;" : "=r"(r) : "f"(x));
    return r;
}

__device__ __forceinline__ void mma_tf32(float* c, const uint32_t* a, const uint32_t* b) {
    asm volatile(
        "mma.sync.aligned.m16n8k8.row.col.f32.tf32.tf32.f32 "
        "{%0,%1,%2,%3},{%4,%5,%6,%7},{%8,%9},{%0,%1,%2,%3};"
        : "+f"(c[0]), "+f"(c[1]), "+f"(c[2]), "+f"(c[3])
        : "r"(a[0]), "r"(a[1]), "r"(a[2]), "r"(a[3]), "r"(b[0]), "r"(b[1]));
}

// packed fp32x2 ops (sm_103a FFMA2 path — PTX-only)
typedef unsigned long long u64t;
__device__ __forceinline__ u64t pk2(float v) {
    u64t r; asm("mov.b64 %0, {%1, %1};" : "=l"(r) : "f"(v)); return r;
}
__device__ __forceinline__ u64t fma2(u64t a, u64t b, u64t c) {
    u64t d; asm("fma.rn.f32x2 %0, %1, %2, %3;" : "=l"(d) : "l"(a), "l"(b), "l"(c)); return d;
}
__device__ __forceinline__ u64t mul2(u64t a, u64t b) {
    u64t d; asm("mul.rn.f32x2 %0, %1, %2;" : "=l"(d) : "l"(a), "l"(b)); return d;
}
__device__ __forceinline__ float hadd2(u64t a) {
    float lo, hi; asm("mov.b64 {%0, %1}, %2;" : "=f"(lo), "=f"(hi) : "l"(a)); return lo + hi;
}

// ---------------- tf32 GEMM: C[M,N] = A[M,K] @ W[N,K]^T ----------------
// BM=128, BN=128, BK=32, 256 threads (8 warps as 2x4), warp tile 64x32.
// Register-staged pipeline: preload next K-tile to regs during compute.
#define LDS_STRIDE 36

__device__ __forceinline__ uint4 cvt4(float4 v) {
    uint4 r;
    r.x = f2tf(v.x); r.y = f2tf(v.y); r.z = f2tf(v.z); r.w = f2tf(v.w);
    return r;
}

__global__ __launch_bounds__(256) void gemm_tf32(
    const float* __restrict__ A, int lda, int flipA,
    const float* __restrict__ W, int ldw,
    float* __restrict__ C, int ldc,
    int M, int N, int K)
{
    __shared__ uint32_t As[128 * LDS_STRIDE];
    __shared__ uint32_t Ws[128 * LDS_STRIDE];

    const int tid  = threadIdx.x;
    const int warp = tid >> 5, lane = tid & 31;
    const int g = lane >> 2, tg = lane & 3;
    const int wm = warp >> 2, wn = warp & 3;      // 2 x 4 warp grid
    const int mblk = blockIdx.y * 128;
    const int nblk = blockIdx.x * 128;
    const int m0 = wm * 64, n0 = wn * 32;

    // loader coordinates (each thread: 4 float4 per matrix per K-tile)
    const int lm = tid >> 3;               // 0..31 base row
    const int lk = (tid & 7) << 2;         // k offset within 32

    float4 ra[4], rw[4];

    // preload kt = 0
#pragma unroll
    for (int i = 0; i < 4; i++) {
        int gr = mblk + lm + i * 32;
        int row = flipA ? (M - 1 - gr) : gr;
        ra[i] = *reinterpret_cast<const float4*>(A + (size_t)row * lda + lk);
        int gn = nblk + lm + i * 32;
        rw[i] = (gn < N) ? *reinterpret_cast<const float4*>(W + (size_t)gn * ldw + lk)
                         : make_float4(0.f, 0.f, 0.f, 0.f);
    }

    float acc[4][4][4];
#pragma unroll
    for (int i = 0; i < 4; i++)
#pragma unroll
        for (int j = 0; j < 4; j++)
#pragma unroll
            for (int r = 0; r < 4; r++) acc[i][j][r] = 0.f;

    for (int kt = 0; kt < K; kt += 32) {
        // commit staged regs to smem (tf32-converted)
#pragma unroll
        for (int i = 0; i < 4; i++) {
            *reinterpret_cast<uint4*>(&As[(lm + i * 32) * LDS_STRIDE + lk]) = cvt4(ra[i]);
            *reinterpret_cast<uint4*>(&Ws[(lm + i * 32) * LDS_STRIDE + lk]) = cvt4(rw[i]);
        }
        __syncthreads();

        // preload next tile while computing this one
        if (kt + 32 < K) {
#pragma unroll
            for (int i = 0; i < 4; i++) {
                int gr = mblk + lm + i * 32;
                int row = flipA ? (M - 1 - gr) : gr;
                ra[i] = *reinterpret_cast<const float4*>(A + (size_t)row * lda + kt + 32 + lk);
                int gn = nblk + lm + i * 32;
                rw[i] = (gn < N) ? *reinterpret_cast<const float4*>(W + (size_t)gn * ldw + kt + 32 + lk)
                                 : make_float4(0.f, 0.f, 0.f, 0.f);
            }
        }

#pragma unroll
        for (int ks = 0; ks < 4; ks++) {
            const int k0 = ks * 8;
            uint32_t a[4][4], b[4][2];
#pragma unroll
            for (int mt = 0; mt < 4; mt++) {
                int row = m0 + mt * 16 + g;
                a[mt][0] = As[row * LDS_STRIDE + k0 + tg];
                a[mt][1] = As[(row + 8) * LDS_STRIDE + k0 + tg];
                a[mt][2] = As[row * LDS_STRIDE + k0 + tg + 4];
                a[mt][3] = As[(row + 8) * LDS_STRIDE + k0 + tg + 4];
            }
#pragma unroll
            for (int nt = 0; nt < 4; nt++) {
                int col = n0 + nt * 8 + g;
                b[nt][0] = Ws[col * LDS_STRIDE + k0 + tg];
                b[nt][1] = Ws[col * LDS_STRIDE + k0 + tg + 4];
            }
#pragma unroll
            for (int mt = 0; mt < 4; mt++)
#pragma unroll
                for (int nt = 0; nt < 4; nt++)
                    mma_tf32(acc[mt][nt], a[mt], b[nt]);
        }
        __syncthreads();
    }

    // epilogue
#pragma unroll
    for (int mt = 0; mt < 4; mt++) {
#pragma unroll
        for (int nt = 0; nt < 4; nt++) {
            int row = mblk + m0 + mt * 16 + g;
            int col = nblk + n0 + nt * 8 + 2 * tg;
            if (col < N) {
                C[(size_t)row * ldc + col]           = acc[mt][nt][0];
                C[(size_t)(row + 8) * ldc + col]     = acc[mt][nt][2];
            }
            if (col + 1 < N) {
                C[(size_t)row * ldc + col + 1]       = acc[mt][nt][1];
                C[(size_t)(row + 8) * ldc + col + 1] = acc[mt][nt][3];
            }
        }
    }
}

// ---------------- prep: causal dwconv + silu, dt softplus, dA, dtx ----------------
__global__ __launch_bounds__(256) void prep_kernel(
    const float* __restrict__ cw_f, const float* __restrict__ cb_f,
    const float* __restrict__ cw_b, const float* __restrict__ cb_b,
    const float* __restrict__ dtb_f, const float* __restrict__ dtb_b,
    const float* __restrict__ Alog_f, const float* __restrict__ Alog_b)
{
    const int l = blockIdx.x, dir = blockIdx.y, tid = threadIdx.x;
    const float* cw   = dir ? cw_b   : cw_f;
    const float* cb   = dir ? cb_b   : cb_f;
    const float* dtb  = dir ? dtb_b  : dtb_f;
    const float* Alog = dir ? Alog_b : Alog_f;

    const size_t base = (size_t)dir * L_SEQ + l;
    const float* zrow = g_zx + base * DPROJ;

    __shared__ float sdt[NH];
    if (tid < NH) {
        float dt = softplus_f(zrow[4224 + tid] + dtb[tid]);
        sdt[tid] = dt;
        g_dA[base * NH + tid] = expf(-expf(Alog[tid]) * dt);
    }
    __syncthreads();

    for (int c = tid; c < CONVD; c += 256) {
        float s = cb[c];
#pragma unroll
        for (int t = 0; t < 4; t++) {
            int lp = l - 3 + t;
            if (lp >= 0)
                s = fmaf(cw[c * 4 + t],
                         g_zx[((size_t)dir * L_SEQ + lp) * DPROJ + 2048 + c], s);
        }
        float v = silu_f(s);
        if (c < DINNER) {
            g_x[base * DINNER + c]   = v;
            g_dtx[base * DINNER + c] = sdt[c >> 6] * v;
        } else if (c < 2112) {
            g_Bv[base * NST + (c - 2048)] = v;
        } else {
            g_Cv[base * NST + (c - 2112)] = v;
        }
    }
}

// ---------------- sequential SSM scan (f32x2 packed, 512 threads) ----------------
// grid (2 p-slices, 32 heads, 2 dirs) = 128 blocks, 512 threads (4 warps/SMSP).
// thread t: pl = t>>4 (p within slice, 0..31), q = t&15 owns n in [q*4, q*4+4) = 2 pairs.
#define SCH 16

__global__ __launch_bounds__(512) void scan_kernel()
{
    const int ps = blockIdx.x, hh = blockIdx.y, dir = blockIdx.z;
    const int tid = threadIdx.x;
    const int pl = tid >> 4, q = tid & 15;

    __shared__ float sB[SCH][64], sC[SCH][64], sdt[SCH][32], sdA[SCH];

    u64t h0 = 0ull, h1 = 0ull;

    const size_t dbase = (size_t)dir * L_SEQ;
    const int pcol = hh * HD + ps * 32;

    for (int c0 = 0; c0 < L_SEQ; c0 += SCH) {
        // stage chunk (B/C contiguous across SCH steps: 256 float4 each)
        if (tid < 256) {
            reinterpret_cast<float4*>(sB)[tid] =
                reinterpret_cast<const float4*>(g_Bv + (dbase + c0) * NST)[tid];
        } else {
            reinterpret_cast<float4*>(sC)[tid - 256] =
                reinterpret_cast<const float4*>(g_Cv + (dbase + c0) * NST)[tid - 256];
        }
        if (tid < 128) {
            int s = tid >> 3, cc = (tid & 7) << 2;
            *reinterpret_cast<float4*>(&sdt[s][cc]) =
                *reinterpret_cast<const float4*>(g_dtx + (dbase + c0 + s) * DINNER + pcol + cc);
        }
        if (tid < SCH) sdA[tid] = g_dA[(dbase + c0 + tid) * NH + hh];
        __syncthreads();

#pragma unroll
        for (int s = 0; s < SCH; s++) {
            const u64t dA2 = pk2(sdA[s]);
            const u64t dt2 = pk2(sdt[s][pl]);
            ulonglong2 b2 = *reinterpret_cast<const ulonglong2*>(&sB[s][q * 4]);
            ulonglong2 c2 = *reinterpret_cast<const ulonglong2*>(&sC[s][q * 4]);
            h0 = fma2(h0, dA2, mul2(dt2, b2.x));
            h1 = fma2(h1, dA2, mul2(dt2, b2.y));
            u64t acc = fma2(h1, c2.y, mul2(h0, c2.x));
            float a = hadd2(acc);
            a += __shfl_xor_sync(0xffffffffu, a, 1);
            a += __shfl_xor_sync(0xffffffffu, a, 2);
            a += __shfl_xor_sync(0xffffffffu, a, 4);
            a += __shfl_xor_sync(0xffffffffu, a, 8);
            if (q == 0)
                g_y[(dbase + c0 + s) * DINNER + pcol + pl] = a;
        }
        __syncthreads();
    }
}

// ---------------- gate: y + D*x, *silu(z), rmsnorm, *norm_w ----------------
__global__ __launch_bounds__(256) void gate_kernel(
    const float* __restrict__ D_f, const float* __restrict__ D_b,
    const float* __restrict__ nw_f, const float* __restrict__ nw_b)
{
    const int l = blockIdx.x, dir = blockIdx.y, tid = threadIdx.x;
    const float* Dp = dir ? D_b : D_f;
    const float* nw = dir ? nw_b : nw_f;
    const size_t base = (size_t)dir * L_SEQ + l;

    float ss = 0.f;
    for (int c = tid; c < DINNER; c += 256) {
        float y = g_y[base * DINNER + c] + Dp[c >> 6] * g_x[base * DINNER + c];
        float z = g_zx[base * DPROJ + c];
        float yg = y * silu_f(z);
        g_ygn[base * DINNER + c] = yg;
        ss = fmaf(yg, yg, ss);
    }
    __shared__ float red[8];
#pragma unroll
    for (int o = 16; o; o >>= 1) ss += __shfl_xor_sync(0xffffffffu, ss, o);
    if ((tid & 31) == 0) red[tid >> 5] = ss;
    __syncthreads();
    if (tid < 8) {
        float v = red[tid];
#pragma unroll
        for (int o = 4; o; o >>= 1) v += __shfl_xor_sync(0xffu, v, o);
        if (tid == 0) red[0] = v;
    }
    __syncthreads();
    const float scale = rsqrtf(red[0] * (1.f / DINNER) + 1e-5f);
    for (int c = tid; c < DINNER; c += 256)
        g_ygn[base * DINNER + c] *= scale * nw[c];
}

// ---------------- combine: silu(concat(out_f, flip(out_b))) ----------------
__global__ __launch_bounds__(256) void combine_kernel()
{
    const int l = blockIdx.x, tid = threadIdx.x;
    for (int j = tid; j < 2 * DMODEL; j += 256) {
        float v = (j < DMODEL)
            ? g_t[(size_t)l * DMODEL + j]
            : g_t[(size_t)(L_SEQ + (L_SEQ - 1 - l)) * DMODEL + (j - DMODEL)];
        g_G[(size_t)l * 2 * DMODEL + j] = silu_f(v);
    }
}

// ---------------- launch ----------------
extern "C" void kernel_launch(void* const* d_in, const int* in_sizes, int n_in,
                              void* d_out, int out_size)
{
    const float* u         = (const float*)d_in[0];
    const float* W_in_f    = (const float*)d_in[1];
    const float* W_in_b    = (const float*)d_in[2];
    const float* conv_w_f  = (const float*)d_in[3];
    const float* conv_b_f  = (const float*)d_in[4];
    const float* conv_w_b  = (const float*)d_in[5];
    const float* conv_b_b  = (const float*)d_in[6];
    const float* dt_bias_f = (const float*)d_in[7];
    const float* dt_bias_b = (const float*)d_in[8];
    const float* A_log_f   = (const float*)d_in[9];
    const float* A_log_b   = (const float*)d_in[10];
    const float* D_f       = (const float*)d_in[11];
    const float* D_b       = (const float*)d_in[12];
    const float* norm_w_f  = (const float*)d_in[13];
    const float* norm_w_b  = (const float*)d_in[14];
    const float* W_out_f   = (const float*)d_in[15];
    const float* W_out_b   = (const float*)d_in[16];
    const float* W_out     = (const float*)d_in[17];

    float *zx, *ygn, *tbuf, *Gm;
    cudaGetSymbolAddress((void**)&zx,   g_zx);
    cudaGetSymbolAddress((void**)&ygn,  g_ygn);
    cudaGetSymbolAddress((void**)&tbuf, g_t);
    cudaGetSymbolAddress((void**)&Gm,   g_G);

    // 1) in_proj both directions (dir1 reads time-flipped u)
    gemm_tf32<<<dim3((DPROJ + 127) / 128, L_SEQ / 128), 256>>>(
        u, DMODEL, 0, W_in_f, DMODEL, zx, DPROJ, L_SEQ, DPROJ, DMODEL);
    gemm_tf32<<<dim3((DPROJ + 127) / 128, L_SEQ / 128), 256>>>(
        u, DMODEL, 1, W_in_b, DMODEL, zx + (size_t)L_SEQ * DPROJ, DPROJ, L_SEQ, DPROJ, DMODEL);

    // 2) conv + silu + dt/dA/dtx
    prep_kernel<<<dim3(L_SEQ, 2), 256>>>(conv_w_f, conv_b_f, conv_w_b, conv_b_b,
                                         dt_bias_f, dt_bias_b, A_log_f, A_log_b);

    // 3) sequential scan
    scan_kernel<<<dim3(2, NH, 2), 512>>>();

    // 4) gate + rmsnorm
    gate_kernel<<<dim3(L_SEQ, 2), 256>>>(D_f, D_b, norm_w_f, norm_w_b);

    // 5) per-direction out projections
    gemm_tf32<<<dim3(DMODEL / 128, L_SEQ / 128), 256>>>(
        ygn, DINNER, 0, W_out_f, DINNER, tbuf, DMODEL, L_SEQ, DMODEL, DINNER);
    gemm_tf32<<<dim3(DMODEL / 128, L_SEQ / 128), 256>>>(
        ygn + (size_t)L_SEQ * DINNER, DINNER, 0, W_out_b, DINNER,
        tbuf + (size_t)L_SEQ * DMODEL, DMODEL, L_SEQ, DMODEL, DINNER);

    // 6) silu(concat) then final projection
    combine_kernel<<<L_SEQ, 256>>>();
    gemm_tf32<<<dim3(DMODEL / 128, L_SEQ / 128), 256>>>(
        Gm, 2 * DMODEL, 0, W_out, 2 * DMODEL, (float*)d_out, DMODEL,
        L_SEQ, DMODEL, 2 * DMODEL);
}

// round 4
// speedup vs baseline: 1.8800x; 1.1610x over previous
#include <cuda_runtime.h>
#include <cstdint>

#define L_SEQ  1024
#define DMODEL 1024
#define DINNER 2048
#define NH     32
#define HD     64
#define NST    64
#define CONVD  2176
#define DPROJ  4256

// ---------------- scratch (static device globals; no allocations) ----------------
__device__ __align__(128) float g_zx [2 * L_SEQ * DPROJ];
__device__ __align__(128) float g_x  [2 * L_SEQ * DINNER];
__device__ __align__(128) float g_dtx[2 * L_SEQ * DINNER];
__device__ __align__(128) float g_dA [2 * L_SEQ * NH];
__device__ __align__(128) float g_Bv [2 * L_SEQ * NST];
__device__ __align__(128) float g_Cv [2 * L_SEQ * NST];
__device__ __align__(128) float g_y  [2 * L_SEQ * DINNER];   // n-half 0 partial
__device__ __align__(128) float g_y2 [2 * L_SEQ * DINNER];   // n-half 1 partial
__device__ __align__(128) float g_ygn[2 * L_SEQ * DINNER];
__device__ __align__(128) float g_t  [2 * L_SEQ * DMODEL];
__device__ __align__(128) float g_G  [L_SEQ * 2 * DMODEL];

// ---------------- helpers ----------------
__device__ __forceinline__ float silu_f(float v) { return v / (1.f + expf(-v)); }
__device__ __forceinline__ float softplus_f(float v) { return v > 20.f ? v : log1pf(expf(v)); }

__device__ __forceinline__ uint32_t f2tf(float x) {
    uint32_t r;
    asm("cvt.rna.tf32.f32 %0, %1;" : "=r"(r) : "f"(x));
    return r;
}

__device__ __forceinline__ void mma_tf32(float* c, const uint32_t* a, const uint32_t* b) {
    asm volatile(
        "mma.sync.aligned.m16n8k8.row.col.f32.tf32.tf32.f32 "
        "{%0,%1,%2,%3},{%4,%5,%6,%7},{%8,%9},{%0,%1,%2,%3};"
        : "+f"(c[0]), "+f"(c[1]), "+f"(c[2]), "+f"(c[3])
        : "r"(a[0]), "r"(a[1]), "r"(a[2]), "r"(a[3]), "r"(b[0]), "r"(b[1]));
}

// packed fp32x2 ops (sm_103a FFMA2 path — PTX-only)
typedef unsigned long long u64t;
__device__ __forceinline__ u64t pk2(float v) {
    u64t r; asm("mov.b64 %0, {%1, %1};" : "=l"(r) : "f"(v)); return r;
}
__device__ __forceinline__ u64t fma2(u64t a, u64t b, u64t c) {
    u64t d; asm("fma.rn.f32x2 %0, %1, %2, %3;" : "=l"(d) : "l"(a), "l"(b), "l"(c)); return d;
}
__device__ __forceinline__ u64t mul2(u64t a, u64t b) {
    u64t d; asm("mul.rn.f32x2 %0, %1, %2;" : "=l"(d) : "l"(a), "l"(b)); return d;
}
__device__ __forceinline__ float hadd2(u64t a) {
    float lo, hi; asm("mov.b64 {%0, %1}, %2;" : "=f"(lo), "=f"(hi) : "l"(a)); return lo + hi;
}

// ---------------- tf32 GEMM: C[M,N] = A[M,K] @ W[N,K]^T ----------------
// BM=128, BN=128, BK=32, 256 threads (8 warps as 2x4), warp tile 64x32.
// Double-buffered dynamic smem; register-staged gmem loads; one sync per K-iter.
// blockIdx.z selects (W0|W1), offsets A/C by strideA/strideC, flip per flip_mode.
#define LDS_STRIDE 36
#define GEMM_SMEM_WORDS (128 * LDS_STRIDE)
#define GEMM_SMEM_BYTES (2 * 2 * GEMM_SMEM_WORDS * 4)

__device__ __forceinline__ uint4 cvt4(float4 v) {
    uint4 r;
    r.x = f2tf(v.x); r.y = f2tf(v.y); r.z = f2tf(v.z); r.w = f2tf(v.w);
    return r;
}

__global__ __launch_bounds__(256) void gemm_tf32(
    const float* __restrict__ A, int lda, int flip_mode,   // 0 none, 2: flip when z==1
    const float* __restrict__ W0, const float* __restrict__ W1, int ldw,
    float* __restrict__ C, int ldc,
    int M, int N, int K, long strideA, long strideC)
{
    extern __shared__ uint32_t smem_dyn[];
    uint32_t* As = smem_dyn;                       // [2][GEMM_SMEM_WORDS]
    uint32_t* Ws = smem_dyn + 2 * GEMM_SMEM_WORDS; // [2][GEMM_SMEM_WORDS]

    const int z = blockIdx.z;
    const float* Ap = A + (size_t)z * strideA;
    const float* W  = z ? W1 : W0;
    float* Cp = C + (size_t)z * strideC;
    const int flipA = (flip_mode == 2 && z == 1);

    const int tid  = threadIdx.x;
    const int warp = tid >> 5, lane = tid & 31;
    const int g = lane >> 2, tg = lane & 3;
    const int wm = warp >> 2, wn = warp & 3;      // 2 x 4 warp grid
    const int mblk = blockIdx.y * 128;
    const int nblk = blockIdx.x * 128;
    const int m0 = wm * 64, n0 = wn * 32;

    const int lm = tid >> 3;               // 0..31 base row
    const int lk = (tid & 7) << 2;         // k offset within 32

    float4 ra[4], rw[4];

#define LOAD_TILE(kt_) do {                                                            \
        _Pragma("unroll")                                                              \
        for (int i = 0; i < 4; i++) {                                                  \
            int gr = mblk + lm + i * 32;                                               \
            int row = flipA ? (M - 1 - gr) : gr;                                       \
            ra[i] = *reinterpret_cast<const float4*>(Ap + (size_t)row * lda + (kt_) + lk); \
            int gn = nblk + lm + i * 32;                                               \
            rw[i] = (gn < N) ? *reinterpret_cast<const float4*>(W + (size_t)gn * ldw + (kt_) + lk) \
                             : make_float4(0.f, 0.f, 0.f, 0.f);                        \
        }                                                                              \
    } while (0)

#define COMMIT_TILE(buf_) do {                                                         \
        _Pragma("unroll")                                                              \
        for (int i = 0; i < 4; i++) {                                                  \
            *reinterpret_cast<uint4*>(&As[(buf_) * GEMM_SMEM_WORDS + (lm + i * 32) * LDS_STRIDE + lk]) = cvt4(ra[i]); \
            *reinterpret_cast<uint4*>(&Ws[(buf_) * GEMM_SMEM_WORDS + (lm + i * 32) * LDS_STRIDE + lk]) = cvt4(rw[i]); \
        }                                                                              \
    } while (0)

    LOAD_TILE(0);
    COMMIT_TILE(0);
    __syncthreads();

    float acc[4][4][4];
#pragma unroll
    for (int i = 0; i < 4; i++)
#pragma unroll
        for (int j = 0; j < 4; j++)
#pragma unroll
            for (int r = 0; r < 4; r++) acc[i][j][r] = 0.f;

    int b = 0;
    for (int kt = 0; kt < K; kt += 32) {
        const bool more = (kt + 32 < K);
        if (more) LOAD_TILE(kt + 32);

        const uint32_t* Ab = &As[b * GEMM_SMEM_WORDS];
        const uint32_t* Wb = &Ws[b * GEMM_SMEM_WORDS];
#pragma unroll
        for (int ks = 0; ks < 4; ks++) {
            const int k0 = ks * 8;
            uint32_t a[4][4], bb[4][2];
#pragma unroll
            for (int mt = 0; mt < 4; mt++) {
                int row = m0 + mt * 16 + g;
                a[mt][0] = Ab[row * LDS_STRIDE + k0 + tg];
                a[mt][1] = Ab[(row + 8) * LDS_STRIDE + k0 + tg];
                a[mt][2] = Ab[row * LDS_STRIDE + k0 + tg + 4];
                a[mt][3] = Ab[(row + 8) * LDS_STRIDE + k0 + tg + 4];
            }
#pragma unroll
            for (int nt = 0; nt < 4; nt++) {
                int col = n0 + nt * 8 + g;
                bb[nt][0] = Wb[col * LDS_STRIDE + k0 + tg];
                bb[nt][1] = Wb[col * LDS_STRIDE + k0 + tg + 4];
            }
#pragma unroll
            for (int mt = 0; mt < 4; mt++)
#pragma unroll
                for (int nt = 0; nt < 4; nt++)
                    mma_tf32(acc[mt][nt], a[mt], bb[nt]);
        }
        if (more) {
            COMMIT_TILE(b ^ 1);
            __syncthreads();
        }
        b ^= 1;
    }

    // epilogue
#pragma unroll
    for (int mt = 0; mt < 4; mt++) {
#pragma unroll
        for (int nt = 0; nt < 4; nt++) {
            int row = mblk + m0 + mt * 16 + g;
            int col = nblk + n0 + nt * 8 + 2 * tg;
            if (col < N) {
                Cp[(size_t)row * ldc + col]           = acc[mt][nt][0];
                Cp[(size_t)(row + 8) * ldc + col]     = acc[mt][nt][2];
            }
            if (col + 1 < N) {
                Cp[(size_t)row * ldc + col + 1]       = acc[mt][nt][1];
                Cp[(size_t)(row + 8) * ldc + col + 1] = acc[mt][nt][3];
            }
        }
    }
}

// ---------------- prep: causal dwconv + silu, dt softplus, dA, dtx ----------------
__global__ __launch_bounds__(256) void prep_kernel(
    const float* __restrict__ cw_f, const float* __restrict__ cb_f,
    const float* __restrict__ cw_b, const float* __restrict__ cb_b,
    const float* __restrict__ dtb_f, const float* __restrict__ dtb_b,
    const float* __restrict__ Alog_f, const float* __restrict__ Alog_b)
{
    const int l = blockIdx.x, dir = blockIdx.y, tid = threadIdx.x;
    const float* cw   = dir ? cw_b   : cw_f;
    const float* cb   = dir ? cb_b   : cb_f;
    const float* dtb  = dir ? dtb_b  : dtb_f;
    const float* Alog = dir ? Alog_b : Alog_f;

    const size_t base = (size_t)dir * L_SEQ + l;
    const float* zrow = g_zx + base * DPROJ;

    __shared__ float sdt[NH];
    if (tid < NH) {
        float dt = softplus_f(zrow[4224 + tid] + dtb[tid]);
        sdt[tid] = dt;
        g_dA[base * NH + tid] = expf(-expf(Alog[tid]) * dt);
    }
    __syncthreads();

    for (int c = tid; c < CONVD; c += 256) {
        float s = cb[c];
#pragma unroll
        for (int t = 0; t < 4; t++) {
            int lp = l - 3 + t;
            if (lp >= 0)
                s = fmaf(cw[c * 4 + t],
                         g_zx[((size_t)dir * L_SEQ + lp) * DPROJ + 2048 + c], s);
        }
        float v = silu_f(s);
        if (c < DINNER) {
            g_x[base * DINNER + c]   = v;
            g_dtx[base * DINNER + c] = sdt[c >> 6] * v;
        } else if (c < 2112) {
            g_Bv[base * NST + (c - 2048)] = v;
        } else {
            g_Cv[base * NST + (c - 2112)] = v;
        }
    }
}

// ---------------- sequential SSM scan (f32x2, n-split across blocks) ----------------
// grid 256 = (2 p-half * 2 n-half, 32 heads, 2 dirs), block 256.
// thread t: pl = t>>3 (p within 32-slice), q = t&7 owns 4 n (2 pairs) of the 32-n half.
// Partial y (sum over this n-half) -> g_y / g_y2; gate_kernel adds them.
#define SCH 16

__global__ __launch_bounds__(256) void scan_kernel()
{
    const int ps = blockIdx.x & 1, ns = blockIdx.x >> 1;
    const int hh = blockIdx.y, dir = blockIdx.z;
    const int tid = threadIdx.x;
    const int pl = tid >> 3, q = tid & 7;

    __shared__ __align__(16) float sB[SCH][32], sC[SCH][32], sdt[SCH][32];
    __shared__ float sdA[SCH];

    u64t h0 = 0ull, h1 = 0ull;

    const size_t dbase = (size_t)dir * L_SEQ;
    const int pcol  = hh * HD + ps * 32;
    const int nbase = ns * 32;
    float* yout = ns ? g_y2 : g_y;

    for (int c0 = 0; c0 < L_SEQ; c0 += SCH) {
        // stage chunk (rows stride NST=64 for B/C, DINNER for dtx)
        if (tid < 128) {
            int s = tid >> 3, cc = (tid & 7) << 2;
            *reinterpret_cast<float4*>(&sB[s][cc]) =
                *reinterpret_cast<const float4*>(g_Bv + (dbase + c0 + s) * NST + nbase + cc);
            *reinterpret_cast<float4*>(&sdt[s][cc]) =
                *reinterpret_cast<const float4*>(g_dtx + (dbase + c0 + s) * DINNER + pcol + cc);
        } else {
            int t2 = tid - 128;
            int s = t2 >> 3, cc = (t2 & 7) << 2;
            *reinterpret_cast<float4*>(&sC[s][cc]) =
                *reinterpret_cast<const float4*>(g_Cv + (dbase + c0 + s) * NST + nbase + cc);
            if (t2 < SCH) sdA[t2] = g_dA[(dbase + c0 + t2) * NH + hh];
        }
        __syncthreads();

#pragma unroll
        for (int s = 0; s < SCH; s++) {
            const u64t dA2 = pk2(sdA[s]);
            const u64t dt2 = pk2(sdt[s][pl]);
            ulonglong2 b2 = *reinterpret_cast<const ulonglong2*>(&sB[s][q * 4]);
            ulonglong2 c2 = *reinterpret_cast<const ulonglong2*>(&sC[s][q * 4]);
            h0 = fma2(h0, dA2, mul2(dt2, b2.x));
            h1 = fma2(h1, dA2, mul2(dt2, b2.y));
            u64t acc = fma2(h1, c2.y, mul2(h0, c2.x));
            float a = hadd2(acc);
            a += __shfl_xor_sync(0xffffffffu, a, 1);
            a += __shfl_xor_sync(0xffffffffu, a, 2);
            a += __shfl_xor_sync(0xffffffffu, a, 4);
            if (q == 0)
                yout[(dbase + c0 + s) * DINNER + pcol + pl] = a;
        }
        __syncthreads();
    }
}

// ---------------- gate: (y0+y1) + D*x, *silu(z), rmsnorm, *norm_w ----------------
__global__ __launch_bounds__(256) void gate_kernel(
    const float* __restrict__ D_f, const float* __restrict__ D_b,
    const float* __restrict__ nw_f, const float* __restrict__ nw_b)
{
    const int l = blockIdx.x, dir = blockIdx.y, tid = threadIdx.x;
    const float* Dp = dir ? D_b : D_f;
    const float* nw = dir ? nw_b : nw_f;
    const size_t base = (size_t)dir * L_SEQ + l;

    float ss = 0.f;
    for (int c = tid; c < DINNER; c += 256) {
        float y = g_y[base * DINNER + c] + g_y2[base * DINNER + c]
                + Dp[c >> 6] * g_x[base * DINNER + c];
        float z = g_zx[base * DPROJ + c];
        float yg = y * silu_f(z);
        g_ygn[base * DINNER + c] = yg;
        ss = fmaf(yg, yg, ss);
    }
    __shared__ float red[8];
#pragma unroll
    for (int o = 16; o; o >>= 1) ss += __shfl_xor_sync(0xffffffffu, ss, o);
    if ((tid & 31) == 0) red[tid >> 5] = ss;
    __syncthreads();
    if (tid < 8) {
        float v = red[tid];
#pragma unroll
        for (int o = 4; o; o >>= 1) v += __shfl_xor_sync(0xffu, v, o);
        if (tid == 0) red[0] = v;
    }
    __syncthreads();
    const float scale = rsqrtf(red[0] * (1.f / DINNER) + 1e-5f);
    for (int c = tid; c < DINNER; c += 256)
        g_ygn[base * DINNER + c] *= scale * nw[c];
}

// ---------------- combine: silu(concat(out_f, flip(out_b))) ----------------
__global__ __launch_bounds__(256) void combine_kernel()
{
    const int l = blockIdx.x, tid = threadIdx.x;
    for (int j = tid; j < 2 * DMODEL; j += 256) {
        float v = (j < DMODEL)
            ? g_t[(size_t)l * DMODEL + j]
            : g_t[(size_t)(L_SEQ + (L_SEQ - 1 - l)) * DMODEL + (j - DMODEL)];
        g_G[(size_t)l * 2 * DMODEL + j] = silu_f(v);
    }
}

// ---------------- launch ----------------
extern "C" void kernel_launch(void* const* d_in, const int* in_sizes, int n_in,
                              void* d_out, int out_size)
{
    const float* u         = (const float*)d_in[0];
    const float* W_in_f    = (const float*)d_in[1];
    const float* W_in_b    = (const float*)d_in[2];
    const float* conv_w_f  = (const float*)d_in[3];
    const float* conv_b_f  = (const float*)d_in[4];
    const float* conv_w_b  = (const float*)d_in[5];
    const float* conv_b_b  = (const float*)d_in[6];
    const float* dt_bias_f = (const float*)d_in[7];
    const float* dt_bias_b = (const float*)d_in[8];
    const float* A_log_f   = (const float*)d_in[9];
    const float* A_log_b   = (const float*)d_in[10];
    const float* D_f       = (const float*)d_in[11];
    const float* D_b       = (const float*)d_in[12];
    const float* norm_w_f  = (const float*)d_in[13];
    const float* norm_w_b  = (const float*)d_in[14];
    const float* W_out_f   = (const float*)d_in[15];
    const float* W_out_b   = (const float*)d_in[16];
    const float* W_out     = (const float*)d_in[17];

    static int attr_done = 0;
    if (!attr_done) {
        cudaFuncSetAttribute(gemm_tf32, cudaFuncAttributeMaxDynamicSharedMemorySize,
                             GEMM_SMEM_BYTES);
        attr_done = 1;
    }

    float *zx, *ygn, *tbuf, *Gm;
    cudaGetSymbolAddress((void**)&zx,   g_zx);
    cudaGetSymbolAddress((void**)&ygn,  g_ygn);
    cudaGetSymbolAddress((void**)&tbuf, g_t);
    cudaGetSymbolAddress((void**)&Gm,   g_G);

    // 1) in_proj, both directions in one launch (z=dir; flip A rows when z==1)
    gemm_tf32<<<dim3((DPROJ + 127) / 128, L_SEQ / 128, 2), 256, GEMM_SMEM_BYTES>>>(
        u, DMODEL, 2, W_in_f, W_in_b, DMODEL, zx, DPROJ,
        L_SEQ, DPROJ, DMODEL, 0, (long)L_SEQ * DPROJ);

    // 2) conv + silu + dt/dA/dtx
    prep_kernel<<<dim3(L_SEQ, 2), 256>>>(conv_w_f, conv_b_f, conv_w_b, conv_b_b,
                                         dt_bias_f, dt_bias_b, A_log_f, A_log_b);

    // 3) sequential scan (p-half x n-half x head x dir)
    scan_kernel<<<dim3(4, NH, 2), 256>>>();

    // 4) gate + rmsnorm
    gate_kernel<<<dim3(L_SEQ, 2), 256>>>(D_f, D_b, norm_w_f, norm_w_b);

    // 5) per-direction out projections, one launch (z selects weights)
    gemm_tf32<<<dim3(DMODEL / 128, L_SEQ / 128, 2), 256, GEMM_SMEM_BYTES>>>(
        ygn, DINNER, 0, W_out_f, W_out_b, DINNER, tbuf, DMODEL,
        L_SEQ, DMODEL, DINNER, (long)L_SEQ * DINNER, (long)L_SEQ * DMODEL);

    // 6) silu(concat) then final projection
    combine_kernel<<<L_SEQ, 256>>>();
    gemm_tf32<<<dim3(DMODEL / 128, L_SEQ / 128, 1), 256, GEMM_SMEM_BYTES>>>(
        Gm, 2 * DMODEL, 0, W_out, W_out, 2 * DMODEL, (float*)d_out, DMODEL,
        L_SEQ, DMODEL, 2 * DMODEL, 0, 0);
}